// round 16
// baseline (speedup 1.0000x reference)
#include <cuda_runtime.h>
#include <cuda_fp16.h>
#include <cstdint>

// Problem dims (fixed)
#define B_  16
#define S_  2048
#define D_  1024
#define H_  1024
#define M_  (B_ * S_)   // 32768
#define N_  (3 * H_)    // 3072
#define K_  D_          // 1024

// ---------------- scratch (__device__ globals; no runtime alloc) ----------
__device__ __half g_A16[(size_t)M_ * K_];
__device__ __half g_W16[(size_t)N_ * K_];
__device__ __half g_z16[(size_t)M_ * H_];
__device__ __half g_f16[(size_t)M_ * H_];
__device__ __half g_o16[(size_t)M_ * H_];   // stores sigmoid(o)

#define NCK 16                 // scan chunks along S
#define CHN (B_ * H_)          // 16384 channels
__device__ float g_cA[NCK * CHN];
__device__ float g_ch[NCK * CHN];
__device__ float g_cHin[NCK * CHN];

// ---------------- helpers -------------------------------------------------
__device__ __forceinline__ uint32_t smem_u32(const void* p) {
    uint32_t a;
    asm("{ .reg .u64 t; cvta.to.shared.u64 t, %1; cvt.u32.u64 %0, t; }" : "=r"(a) : "l"(p));
    return a;
}
__device__ __forceinline__ void cp16(uint32_t saddr, const void* g) {
    asm volatile("cp.async.cg.shared.global [%0], [%1], 16;" :: "r"(saddr), "l"(g) : "memory");
}
#define CP_COMMIT() asm volatile("cp.async.commit_group;" ::: "memory")
#define CP_WAIT1()  asm volatile("cp.async.wait_group 1;" ::: "memory")

#define LDSM_X4(r0, r1, r2, r3, addr)                                          \
    asm volatile("ldmatrix.sync.aligned.m8n8.x4.shared.b16 {%0,%1,%2,%3}, [%4];" \
                 : "=r"(r0), "=r"(r1), "=r"(r2), "=r"(r3) : "r"(addr))

#define MMAF16(c, a, b0v, b1v)                                                 \
    asm volatile("mma.sync.aligned.m16n8k16.row.col.f32.f16.f16.f32 "          \
                 "{%0,%1,%2,%3},{%4,%5,%6,%7},{%8,%9},{%0,%1,%2,%3};"          \
                 : "+f"((c)[0]), "+f"((c)[1]), "+f"((c)[2]), "+f"((c)[3])      \
                 : "r"((a)[0]), "r"((a)[1]), "r"((a)[2]), "r"((a)[3]),         \
                   "r"(b0v), "r"(b1v))

#define SW128(o) ((o) ^ (((o) >> 3) & 0x70))

__device__ __forceinline__ float tanh_fast(float x) {
    float y; asm("tanh.approx.f32 %0, %1;" : "=f"(y) : "f"(x)); return y;
}
__device__ __forceinline__ float sigmoid_fast(float x) {
    return 0.5f * tanh_fast(0.5f * x) + 0.5f;
}

// ---------------- fp32 -> fp16 convert (A and W merged) ------------------
#define NA4 (M_ * K_ / 4)     // 8388608 float4s for A
#define NW4 (N_ * K_ / 4)     // 786432 float4s for W
__global__ __launch_bounds__(256) void convert_kernel(const float* __restrict__ inp,
                                                      const float* __restrict__ W) {
    int i = blockIdx.x * blockDim.x + threadIdx.x;
    const float* src;
    __half2* dst;
    int j;
    if (i < NA4) {
        src = inp; dst = (__half2*)g_A16; j = i;
    } else if (i < NA4 + NW4) {
        src = W; dst = (__half2*)g_W16; j = i - NA4;
    } else {
        return;
    }
    float4 v = ((const float4*)src)[j];
    dst[2 * j]     = __halves2half2(__float2half_rn(v.x), __float2half_rn(v.y));
    dst[2 * j + 1] = __halves2half2(__float2half_rn(v.z), __float2half_rn(v.w));
}

// ---------------- fp16 mma.sync GEMM: D = A16 * W16^T --------------------
// 16 k-chunks of 64 fp16. Stage = A tile + B tile = 32 KB.
// STAGES=3 -> 96 KB smem -> 2 CTAs/SM. Mainloop frozen since R9 (no-spill).
#define BM 128
#define BN 128
#define BKB 128                 // 64 fp16 = 128 bytes per row per stage
#define KCH 16
#define STAGES 3
#define ATILE (BM * BKB)        // 16 KB
#define BTILE (BN * BKB)        // 16 KB
#define STAGEB (ATILE + BTILE)  // 32 KB
#define SMEM_TOTAL (STAGES * STAGEB)  // 96 KB

__global__ __launch_bounds__(256, 2) void gemm_fp16_kernel(const float* __restrict__ bias) {
    extern __shared__ char smem[];
    const uint32_t sbase = smem_u32(smem);
    const int tid = threadIdx.x;
    const int wid = tid >> 5, lid = tid & 31;
    const int wm = wid & 3;          // 4 warp-rows of 32
    const int wn = wid >> 2;         // 2 warp-cols of 64
    const int bm = blockIdx.y * BM, bn = blockIdx.x * BN;

    float acc[2][8][4];
#pragma unroll
    for (int a = 0; a < 2; a++)
#pragma unroll
        for (int b = 0; b < 8; b++)
#pragma unroll
            for (int c = 0; c < 4; c++) acc[a][b][c] = 0.0f;

    auto load_chunk = [&](int j) {
        const size_t kb = (size_t)j * BKB;
        const char* Asrc = (const char*)g_A16 + (size_t)bm * (K_ * 2) + kb;
        const char* Bsrc = (const char*)g_W16 + (size_t)bn * (K_ * 2) + kb;
        const uint32_t stb = sbase + (j % STAGES) * STAGEB;
#pragma unroll
        for (int q = 0; q < 4; q++) {
            int idx = tid + q * 256;
            int r = idx >> 3, c = idx & 7;
            uint32_t so = SW128(r * BKB + c * 16);
            cp16(stb + so, Asrc + (size_t)r * (K_ * 2) + c * 16);
            cp16(stb + ATILE + so, Bsrc + (size_t)r * (K_ * 2) + c * 16);
        }
    };

    // prologue: chunks 0,1
#pragma unroll
    for (int s = 0; s < STAGES - 1; s++) {
        load_chunk(s);
        CP_COMMIT();
    }

    const int lr = lid & 15;         // ldmatrix row-in-tile
    const int lk = (lid >> 4) * 16;  // ldmatrix k-half byte offset

    for (int i = 0; i < KCH; i++) {
        CP_WAIT1();                  // chunk i resident (own groups)
        __syncthreads();             // chunk i visible; compute(i-1) done everywhere
        // stage (i+2)%3 == (i-1)%3: safe to overwrite after the sync above.
        if (i + STAGES - 1 < KCH) load_chunk(i + STAGES - 1);
        CP_COMMIT();

        const uint32_t sA = sbase + (i % STAGES) * STAGEB;
        const uint32_t sB = sA + ATILE;

        uint32_t af[2][2][4], bf[2][4][4];
        // prefetch k-step 0 fragments
#pragma unroll
        for (int mt = 0; mt < 2; mt++) {
            uint32_t ad = sA + SW128((wm * 32 + mt * 16 + lr) * BKB + lk);
            LDSM_X4(af[0][mt][0], af[0][mt][1], af[0][mt][2], af[0][mt][3], ad);
        }
#pragma unroll
        for (int g = 0; g < 4; g++) {
            uint32_t bd = sB + SW128((wn * 64 + g * 16 + lr) * BKB + lk);
            LDSM_X4(bf[0][g][0], bf[0][g][1], bf[0][g][2], bf[0][g][3], bd);
        }
#pragma unroll
        for (int ks = 0; ks < 4; ks++) {
            const int cur = ks & 1, nxt = cur ^ 1;
            if (ks < 3) {
                const int kb2 = (ks + 1) * 32 + lk;
#pragma unroll
                for (int mt = 0; mt < 2; mt++) {
                    uint32_t ad = sA + SW128((wm * 32 + mt * 16 + lr) * BKB + kb2);
                    LDSM_X4(af[nxt][mt][0], af[nxt][mt][1], af[nxt][mt][2], af[nxt][mt][3], ad);
                }
#pragma unroll
                for (int g = 0; g < 4; g++) {
                    uint32_t bd = sB + SW128((wn * 64 + g * 16 + lr) * BKB + kb2);
                    LDSM_X4(bf[nxt][g][0], bf[nxt][g][1], bf[nxt][g][2], bf[nxt][g][3], bd);
                }
            }
#pragma unroll
            for (int mt = 0; mt < 2; mt++)
#pragma unroll
                for (int g = 0; g < 4; g++) {
                    MMAF16(acc[mt][2 * g],     af[cur][mt], bf[cur][g][0], bf[cur][g][2]);
                    MMAF16(acc[mt][2 * g + 1], af[cur][mt], bf[cur][g][1], bf[cur][g][3]);
                }
        }
    }

    // ---- epilogue: bias + activation -> fp16 g_z16 / g_f16 / g_o16 ----
    const int gate = bn >> 10;       // 0=z(tanh) 1=f(sig) 2=sig(o)
    __half* dst = (gate == 0) ? g_z16 : (gate == 1) ? g_f16 : g_o16;
    const int hbase = bn & (H_ - 1);
#pragma unroll
    for (int mt = 0; mt < 2; mt++) {
        const int r0 = bm + wm * 32 + mt * 16 + (lid >> 2);
#pragma unroll
        for (int g = 0; g < 8; g++) {
            const int nl = wn * 64 + g * 8 + (lid & 3) * 2;
            const float b0 = bias[bn + nl], b1 = bias[bn + nl + 1];
            float v0 = acc[mt][g][0] + b0, v1 = acc[mt][g][1] + b1;
            float v2 = acc[mt][g][2] + b0, v3 = acc[mt][g][3] + b1;
            float r0v, r1v, r2v, r3v;
            if (gate == 0) {
                r0v = tanh_fast(v0); r1v = tanh_fast(v1);
                r2v = tanh_fast(v2); r3v = tanh_fast(v3);
            } else {
                r0v = sigmoid_fast(v0); r1v = sigmoid_fast(v1);
                r2v = sigmoid_fast(v2); r3v = sigmoid_fast(v3);
            }
            *(__half2*)&dst[(size_t)r0 * H_ + hbase + nl] = __floats2half2_rn(r0v, r1v);
            *(__half2*)&dst[(size_t)(r0 + 8) * H_ + hbase + nl] = __floats2half2_rn(r2v, r3v);
        }
    }
}

// ---------------- parallel scan: chunked linear recurrence ---------------
// ONE channel per thread (262144 threads) for high occupancy / MLP.
#define CKLEN (S_ / NCK)   // 128

__global__ __launch_bounds__(256) void scan_p1() {
    const int idx = blockIdx.x * 256 + threadIdx.x;    // 0 .. NCK*CHN-1
    const int ch = idx & (CHN - 1);
    const int ck = idx >> 14;                          // CHN = 2^14
    const int b = ch >> 10, h = ch & (H_ - 1);
    size_t base = ((size_t)(b * S_ + ck * CKLEN)) * H_ + h;
    float A = 1.0f, hh = 0.0f;
#pragma unroll 4
    for (int s = 0; s < CKLEN; s++) {
        size_t off = base + (size_t)s * H_;
        float f = __half2float(g_f16[off]);
        float z = __half2float(g_z16[off]);
        hh = fmaf(f, z - hh, hh);
        A *= (1.0f - f);
    }
    g_cA[idx] = A;
    g_ch[idx] = hh;
}

__global__ __launch_bounds__(128) void carry_kernel(float* __restrict__ out) {
    const int ch = blockIdx.x * blockDim.x + threadIdx.x;   // 0..CHN-1
    float Hc = 0.0f;
#pragma unroll
    for (int ck = 0; ck < NCK; ck++) {
        g_cHin[ck * CHN + ch] = Hc;
        Hc = g_ch[ck * CHN + ch] + g_cA[ck * CHN + ch] * Hc;
    }
    out[(size_t)M_ * H_ + ch] = Hc;                         // c_last [B,H]
}

__global__ __launch_bounds__(256) void scan_p2(float* __restrict__ out) {
    const int idx = blockIdx.x * 256 + threadIdx.x;    // 0 .. NCK*CHN-1
    const int ch = idx & (CHN - 1);
    const int ck = idx >> 14;
    const int b = ch >> 10, h = ch & (H_ - 1);
    size_t base = ((size_t)(b * S_ + ck * CKLEN)) * H_ + h;
    float hh = g_cHin[idx];
#pragma unroll 4
    for (int s = 0; s < CKLEN; s++) {
        size_t off = base + (size_t)s * H_;
        float f = __half2float(g_f16[off]);
        float z = __half2float(g_z16[off]);
        float o = __half2float(g_o16[off]);
        hh = fmaf(f, z - hh, hh);
        out[off] = o * hh;
    }
}

// -------------------------------------------------------------------------
extern "C" void kernel_launch(void* const* d_in, const int* in_sizes, int n_in,
                              void* d_out, int out_size) {
    const float* inp  = (const float*)d_in[0];
    const float* W    = (const float*)d_in[1];
    const float* bias = (const float*)d_in[2];
    float* out = (float*)d_out;

    convert_kernel<<<(NA4 + NW4 + 255) / 256, 256>>>(inp, W);

    cudaFuncSetAttribute(gemm_fp16_kernel,
                         cudaFuncAttributeMaxDynamicSharedMemorySize, SMEM_TOTAL);
    dim3 grid(N_ / BN, M_ / BM);   // (24, 256)
    gemm_fp16_kernel<<<grid, 256, SMEM_TOTAL>>>(bias);

    scan_p1<<<(NCK * CHN) / 256, 256>>>();
    carry_kernel<<<CHN / 128, 128>>>(out);
    scan_p2<<<(NCK * CHN) / 256, 256>>>(out);
}

// round 17
// speedup vs baseline: 1.0481x; 1.0481x over previous
#include <cuda_runtime.h>
#include <cuda_fp16.h>
#include <cstdint>

// Problem dims (fixed)
#define B_  16
#define S_  2048
#define D_  1024
#define H_  1024
#define M_  (B_ * S_)   // 32768
#define N_  (3 * H_)    // 3072
#define K_  D_          // 1024

// ---------------- scratch (__device__ globals; no runtime alloc) ----------
__device__ __half g_A16[(size_t)M_ * K_];
__device__ __half g_W16[(size_t)N_ * K_];
__device__ __half g_z16[(size_t)M_ * H_];
__device__ __half g_f16[(size_t)M_ * H_];
__device__ __half g_o16[(size_t)M_ * H_];   // stores sigmoid(o)

#define NCK 16                 // scan chunks along S
#define CHN (B_ * H_)          // 16384 channels
__device__ float g_cA[NCK * CHN];
__device__ float g_ch[NCK * CHN];
__device__ float g_cHin[NCK * CHN];

// ---------------- helpers -------------------------------------------------
__device__ __forceinline__ uint32_t smem_u32(const void* p) {
    uint32_t a;
    asm("{ .reg .u64 t; cvta.to.shared.u64 t, %1; cvt.u32.u64 %0, t; }" : "=r"(a) : "l"(p));
    return a;
}
__device__ __forceinline__ void cp16(uint32_t saddr, const void* g) {
    asm volatile("cp.async.cg.shared.global [%0], [%1], 16;" :: "r"(saddr), "l"(g) : "memory");
}
#define CP_COMMIT() asm volatile("cp.async.commit_group;" ::: "memory")
#define CP_WAIT1()  asm volatile("cp.async.wait_group 1;" ::: "memory")

#define LDSM_X4(r0, r1, r2, r3, addr)                                          \
    asm volatile("ldmatrix.sync.aligned.m8n8.x4.shared.b16 {%0,%1,%2,%3}, [%4];" \
                 : "=r"(r0), "=r"(r1), "=r"(r2), "=r"(r3) : "r"(addr))

#define MMAF16(c, a, b0v, b1v)                                                 \
    asm volatile("mma.sync.aligned.m16n8k16.row.col.f32.f16.f16.f32 "          \
                 "{%0,%1,%2,%3},{%4,%5,%6,%7},{%8,%9},{%0,%1,%2,%3};"          \
                 : "+f"((c)[0]), "+f"((c)[1]), "+f"((c)[2]), "+f"((c)[3])      \
                 : "r"((a)[0]), "r"((a)[1]), "r"((a)[2]), "r"((a)[3]),         \
                   "r"(b0v), "r"(b1v))

#define SW128(o) ((o) ^ (((o) >> 3) & 0x70))

__device__ __forceinline__ float tanh_fast(float x) {
    float y; asm("tanh.approx.f32 %0, %1;" : "=f"(y) : "f"(x)); return y;
}
__device__ __forceinline__ float sigmoid_fast(float x) {
    return 0.5f * tanh_fast(0.5f * x) + 0.5f;
}

// ---------------- fp32 -> fp16 converts ----------------------------------
__global__ __launch_bounds__(256) void convertA_kernel(const float* __restrict__ src, int n4) {
    int i = blockIdx.x * blockDim.x + threadIdx.x;
    if (i >= n4) return;
    float4 v = ((const float4*)src)[i];
    __half2* pa = (__half2*)g_A16;
    pa[2 * i]     = __halves2half2(__float2half_rn(v.x), __float2half_rn(v.y));
    pa[2 * i + 1] = __halves2half2(__float2half_rn(v.z), __float2half_rn(v.w));
}
__global__ __launch_bounds__(256) void convertW_kernel(const float* __restrict__ src, int n4) {
    int i = blockIdx.x * blockDim.x + threadIdx.x;
    if (i >= n4) return;
    float4 v = ((const float4*)src)[i];
    __half2* pw = (__half2*)g_W16;
    pw[2 * i]     = __halves2half2(__float2half_rn(v.x), __float2half_rn(v.y));
    pw[2 * i + 1] = __halves2half2(__float2half_rn(v.z), __float2half_rn(v.w));
}

// ---------------- fp16 mma.sync GEMM: D = A16 * W16^T --------------------
// 16 k-chunks of 64 fp16. Stage = A tile + B tile = 32 KB.
// STAGES=3 -> 96 KB smem -> 2 CTAs/SM. Mainloop frozen since R9 (no-spill).
#define BM 128
#define BN 128
#define BKB 128                 // 64 fp16 = 128 bytes per row per stage
#define KCH 16
#define STAGES 3
#define ATILE (BM * BKB)        // 16 KB
#define BTILE (BN * BKB)        // 16 KB
#define STAGEB (ATILE + BTILE)  // 32 KB
#define SMEM_TOTAL (STAGES * STAGEB)  // 96 KB

__global__ __launch_bounds__(256, 2) void gemm_fp16_kernel(const float* __restrict__ bias) {
    extern __shared__ char smem[];
    const uint32_t sbase = smem_u32(smem);
    const int tid = threadIdx.x;
    const int wid = tid >> 5, lid = tid & 31;
    const int wm = wid & 3;          // 4 warp-rows of 32
    const int wn = wid >> 2;         // 2 warp-cols of 64
    const int bm = blockIdx.y * BM, bn = blockIdx.x * BN;

    float acc[2][8][4];
#pragma unroll
    for (int a = 0; a < 2; a++)
#pragma unroll
        for (int b = 0; b < 8; b++)
#pragma unroll
            for (int c = 0; c < 4; c++) acc[a][b][c] = 0.0f;

    auto load_chunk = [&](int j) {
        const size_t kb = (size_t)j * BKB;
        const char* Asrc = (const char*)g_A16 + (size_t)bm * (K_ * 2) + kb;
        const char* Bsrc = (const char*)g_W16 + (size_t)bn * (K_ * 2) + kb;
        const uint32_t stb = sbase + (j % STAGES) * STAGEB;
#pragma unroll
        for (int q = 0; q < 4; q++) {
            int idx = tid + q * 256;
            int r = idx >> 3, c = idx & 7;
            uint32_t so = SW128(r * BKB + c * 16);
            cp16(stb + so, Asrc + (size_t)r * (K_ * 2) + c * 16);
            cp16(stb + ATILE + so, Bsrc + (size_t)r * (K_ * 2) + c * 16);
        }
    };

    // prologue: chunks 0,1
#pragma unroll
    for (int s = 0; s < STAGES - 1; s++) {
        load_chunk(s);
        CP_COMMIT();
    }

    const int lr = lid & 15;         // ldmatrix row-in-tile
    const int lk = (lid >> 4) * 16;  // ldmatrix k-half byte offset

    for (int i = 0; i < KCH; i++) {
        CP_WAIT1();                  // chunk i resident (own groups)
        __syncthreads();             // chunk i visible; compute(i-1) done everywhere
        // stage (i+2)%3 == (i-1)%3: safe to overwrite after the sync above.
        if (i + STAGES - 1 < KCH) load_chunk(i + STAGES - 1);
        CP_COMMIT();

        const uint32_t sA = sbase + (i % STAGES) * STAGEB;
        const uint32_t sB = sA + ATILE;

        uint32_t af[2][2][4], bf[2][4][4];
        // prefetch k-step 0 fragments
#pragma unroll
        for (int mt = 0; mt < 2; mt++) {
            uint32_t ad = sA + SW128((wm * 32 + mt * 16 + lr) * BKB + lk);
            LDSM_X4(af[0][mt][0], af[0][mt][1], af[0][mt][2], af[0][mt][3], ad);
        }
#pragma unroll
        for (int g = 0; g < 4; g++) {
            uint32_t bd = sB + SW128((wn * 64 + g * 16 + lr) * BKB + lk);
            LDSM_X4(bf[0][g][0], bf[0][g][1], bf[0][g][2], bf[0][g][3], bd);
        }
#pragma unroll
        for (int ks = 0; ks < 4; ks++) {
            const int cur = ks & 1, nxt = cur ^ 1;
            if (ks < 3) {
                const int kb2 = (ks + 1) * 32 + lk;
#pragma unroll
                for (int mt = 0; mt < 2; mt++) {
                    uint32_t ad = sA + SW128((wm * 32 + mt * 16 + lr) * BKB + kb2);
                    LDSM_X4(af[nxt][mt][0], af[nxt][mt][1], af[nxt][mt][2], af[nxt][mt][3], ad);
                }
#pragma unroll
                for (int g = 0; g < 4; g++) {
                    uint32_t bd = sB + SW128((wn * 64 + g * 16 + lr) * BKB + kb2);
                    LDSM_X4(bf[nxt][g][0], bf[nxt][g][1], bf[nxt][g][2], bf[nxt][g][3], bd);
                }
            }
#pragma unroll
            for (int mt = 0; mt < 2; mt++)
#pragma unroll
                for (int g = 0; g < 4; g++) {
                    MMAF16(acc[mt][2 * g],     af[cur][mt], bf[cur][g][0], bf[cur][g][2]);
                    MMAF16(acc[mt][2 * g + 1], af[cur][mt], bf[cur][g][1], bf[cur][g][3]);
                }
        }
    }

    // ---- epilogue: bias + activation -> fp16 g_z16 / g_f16 / g_o16 ----
    const int gate = bn >> 10;       // 0=z(tanh) 1=f(sig) 2=sig(o)
    __half* dst = (gate == 0) ? g_z16 : (gate == 1) ? g_f16 : g_o16;
    const int hbase = bn & (H_ - 1);
#pragma unroll
    for (int mt = 0; mt < 2; mt++) {
        const int r0 = bm + wm * 32 + mt * 16 + (lid >> 2);
#pragma unroll
        for (int g = 0; g < 8; g++) {
            const int nl = wn * 64 + g * 8 + (lid & 3) * 2;
            const float b0 = bias[bn + nl], b1 = bias[bn + nl + 1];
            float v0 = acc[mt][g][0] + b0, v1 = acc[mt][g][1] + b1;
            float v2 = acc[mt][g][2] + b0, v3 = acc[mt][g][3] + b1;
            float r0v, r1v, r2v, r3v;
            if (gate == 0) {
                r0v = tanh_fast(v0); r1v = tanh_fast(v1);
                r2v = tanh_fast(v2); r3v = tanh_fast(v3);
            } else {
                r0v = sigmoid_fast(v0); r1v = sigmoid_fast(v1);
                r2v = sigmoid_fast(v2); r3v = sigmoid_fast(v3);
            }
            *(__half2*)&dst[(size_t)r0 * H_ + hbase + nl] = __floats2half2_rn(r0v, r1v);
            *(__half2*)&dst[(size_t)(r0 + 8) * H_ + hbase + nl] = __floats2half2_rn(r2v, r3v);
        }
    }
}

// ---------------- parallel scan: chunked linear recurrence ---------------
// Each thread handles TWO adjacent channels (half2 loads, float2 stores).
#define CKLEN (S_ / NCK)   // 128
#define CHN2  (CHN / 2)    // 8192 channel pairs

__global__ __launch_bounds__(256) void scan_p1() {
    const int idx = blockIdx.x * 256 + threadIdx.x;    // 0 .. NCK*CHN2-1
    const int cp = idx & (CHN2 - 1);                   // channel pair
    const int ck = idx >> 13;
    const int ch = cp << 1;
    const int b = ch >> 10, h = ch & (H_ - 1);
    size_t base = ((size_t)(b * S_ + ck * CKLEN)) * H_ + h;
    float A0 = 1.0f, A1 = 1.0f, h0 = 0.0f, h1 = 0.0f;
#pragma unroll 8
    for (int s = 0; s < CKLEN; s++) {
        size_t off = base + (size_t)s * H_;
        float2 f2 = __half22float2(*(const __half2*)&g_f16[off]);
        float2 z2 = __half22float2(*(const __half2*)&g_z16[off]);
        h0 = fmaf(f2.x, z2.x - h0, h0);
        h1 = fmaf(f2.y, z2.y - h1, h1);
        A0 *= (1.0f - f2.x);
        A1 *= (1.0f - f2.y);
    }
    *(float2*)&g_cA[ck * CHN + ch] = make_float2(A0, A1);
    *(float2*)&g_ch[ck * CHN + ch] = make_float2(h0, h1);
}

// Carry: prefetch all 16 (A, h) pairs (independent loads -> one DRAM latency),
// then run the dependent recurrence entirely in registers.
__global__ __launch_bounds__(128) void carry_kernel(float* __restrict__ out) {
    const int ch = blockIdx.x * blockDim.x + threadIdx.x;   // 0..CHN-1
    float Av[NCK], hv[NCK];
#pragma unroll
    for (int ck = 0; ck < NCK; ck++) {
        Av[ck] = g_cA[ck * CHN + ch];
        hv[ck] = g_ch[ck * CHN + ch];
    }
    float Hc = 0.0f;
#pragma unroll
    for (int ck = 0; ck < NCK; ck++) {
        g_cHin[ck * CHN + ch] = Hc;
        Hc = hv[ck] + Av[ck] * Hc;
    }
    out[(size_t)M_ * H_ + ch] = Hc;                         // c_last [B,H]
}

__global__ __launch_bounds__(256) void scan_p2(float* __restrict__ out) {
    const int idx = blockIdx.x * 256 + threadIdx.x;
    const int cp = idx & (CHN2 - 1);
    const int ck = idx >> 13;
    const int ch = cp << 1;
    const int b = ch >> 10, h = ch & (H_ - 1);
    size_t base = ((size_t)(b * S_ + ck * CKLEN)) * H_ + h;
    float2 hin = *(const float2*)&g_cHin[ck * CHN + ch];
    float h0 = hin.x, h1 = hin.y;
#pragma unroll 8
    for (int s = 0; s < CKLEN; s++) {
        size_t off = base + (size_t)s * H_;
        float2 f2 = __half22float2(*(const __half2*)&g_f16[off]);
        float2 z2 = __half22float2(*(const __half2*)&g_z16[off]);
        float2 o2 = __half22float2(*(const __half2*)&g_o16[off]);
        h0 = fmaf(f2.x, z2.x - h0, h0);
        h1 = fmaf(f2.y, z2.y - h1, h1);
        *(float2*)&out[off] = make_float2(o2.x * h0, o2.y * h1);
    }
}

// -------------------------------------------------------------------------
extern "C" void kernel_launch(void* const* d_in, const int* in_sizes, int n_in,
                              void* d_out, int out_size) {
    const float* inp  = (const float*)d_in[0];
    const float* W    = (const float*)d_in[1];
    const float* bias = (const float*)d_in[2];
    float* out = (float*)d_out;

    convertA_kernel<<<(M_ * K_ / 4 + 255) / 256, 256>>>(inp, M_ * K_ / 4);
    convertW_kernel<<<(N_ * K_ / 4 + 255) / 256, 256>>>(W, N_ * K_ / 4);

    cudaFuncSetAttribute(gemm_fp16_kernel,
                         cudaFuncAttributeMaxDynamicSharedMemorySize, SMEM_TOTAL);
    dim3 grid(N_ / BN, M_ / BM);   // (24, 256)
    gemm_fp16_kernel<<<grid, 256, SMEM_TOTAL>>>(bias);

    scan_p1<<<(NCK * CHN2) / 256, 256>>>();
    carry_kernel<<<CHN / 128, 128>>>(out);
    scan_p2<<<(NCK * CHN2) / 256, 256>>>(out);
}